// round 6
// baseline (speedup 1.0000x reference)
#include <cuda_runtime.h>
#include <cuda_fp16.h>

#define N_NODES 100000
#define N_EDGES 1600000
#define DIM 64
#define EPS 1e-5f
#define SCAN_B 512

// ---- scratch (device globals; zero-initialized at module load) ----
__device__ __align__(16) __half g_aggh[N_NODES * DIM];  // gathered features (fp16)
__device__ __align__(16) float  g_h2[N_NODES * DIM];    // post-GEMM activations
__device__ __align__(16) __half g_xh[N_NODES * DIM];    // fp16 prescaled x
__device__ int   g_deg_out[N_NODES];   // zeroed at end of final_kernel
__device__ int   g_deg_in[N_NODES];    // zeroed at end of final_kernel
__device__ int   g_off[N_NODES];       // CSR offsets; after fill: end offsets
__device__ int   g_csr[N_EDGES];
__device__ int   g_bsum[SCAN_B];
__device__ int   g_boff[SCAN_B];
__device__ float g_sum[DIM];
__device__ float g_sumsq[DIM];
__device__ float g_scale[DIM];
__device__ float g_shift[DIM];

__device__ __forceinline__ void mma_16816(float* d, const unsigned* a, const unsigned* b) {
    asm volatile(
        "mma.sync.aligned.m16n8k16.row.col.f32.f16.f16.f32 "
        "{%0,%1,%2,%3}, {%4,%5,%6,%7}, {%8,%9}, {%0,%1,%2,%3};"
        : "+f"(d[0]), "+f"(d[1]), "+f"(d[2]), "+f"(d[3])
        : "r"(a[0]), "r"(a[1]), "r"(a[2]), "r"(a[3]), "r"(b[0]), "r"(b[1]));
}

// ---------------------------------------------------------------------------
// 1) degree histogram (both directions), 4 edges per thread via int4
// ---------------------------------------------------------------------------
__global__ void deg_kernel(const int4* __restrict__ src4,
                           const int4* __restrict__ dst4, int e4) {
    int i = blockIdx.x * blockDim.x + threadIdx.x;
    if (i < e4) {
        int4 s = __ldg(src4 + i);
        int4 d = __ldg(dst4 + i);
        atomicAdd(&g_deg_out[s.x], 1); atomicAdd(&g_deg_out[s.y], 1);
        atomicAdd(&g_deg_out[s.z], 1); atomicAdd(&g_deg_out[s.w], 1);
        atomicAdd(&g_deg_in[d.x], 1);  atomicAdd(&g_deg_in[d.y], 1);
        atomicAdd(&g_deg_in[d.z], 1);  atomicAdd(&g_deg_in[d.w], 1);
    }
}

// ---------------------------------------------------------------------------
// 2a) per-block exclusive scan of deg_in
// ---------------------------------------------------------------------------
__global__ void scanA_kernel(int n) {
    __shared__ int sm[SCAN_B];
    int t = threadIdx.x;
    int i = blockIdx.x * SCAN_B + t;
    int v = (i < n) ? g_deg_in[i] : 0;
    sm[t] = v;
    __syncthreads();
    #pragma unroll
    for (int off = 1; off < SCAN_B; off <<= 1) {
        int a = (t >= off) ? sm[t - off] : 0;
        __syncthreads();
        sm[t] += a;
        __syncthreads();
    }
    if (i < n) g_off[i] = sm[t] - v;
    if (t == SCAN_B - 1) g_bsum[blockIdx.x] = sm[t];
}

// ---------------------------------------------------------------------------
// 2b) scan of block sums; also zero BN accumulators
// ---------------------------------------------------------------------------
__global__ void scanB_kernel(int nb) {
    __shared__ int sm[SCAN_B];
    int t = threadIdx.x;
    int v = (t < nb) ? g_bsum[t] : 0;
    sm[t] = v;
    __syncthreads();
    #pragma unroll
    for (int off = 1; off < SCAN_B; off <<= 1) {
        int a = (t >= off) ? sm[t - off] : 0;
        __syncthreads();
        sm[t] += a;
        __syncthreads();
    }
    if (t < nb) g_boff[t] = sm[t] - v;
    if (t < DIM) { g_sum[t] = 0.f; g_sumsq[t] = 0.f; }
}

// ---------------------------------------------------------------------------
// 2c) prep: finalize offsets + prescale xh = fp16(x * norm_src)
// ---------------------------------------------------------------------------
__global__ void prep_kernel(const float4* __restrict__ x4, int n16) {
    int i = blockIdx.x * blockDim.x + threadIdx.x;
    if (i >= n16) return;
    int node = i >> 4;
    int c = i & 15;
    if (c == 0) g_off[node] += g_boff[node >> 9];
    int d = __ldg(&g_deg_out[node]);
    float ns = rsqrtf((float)(d < 1 ? 1 : d));
    float4 v = __ldg(x4 + i);
    __half2 h0 = __floats2half2_rn(v.x * ns, v.y * ns);
    __half2 h1 = __floats2half2_rn(v.z * ns, v.w * ns);
    ((__half2*)g_xh)[i * 2 + 0] = h0;
    ((__half2*)g_xh)[i * 2 + 1] = h1;
}

// ---------------------------------------------------------------------------
// 3) CSR bucket fill: bumps g_off (afterwards g_off[i] = end offset of row i)
// ---------------------------------------------------------------------------
__global__ void fill_kernel(const int4* __restrict__ src4,
                            const int4* __restrict__ dst4, int e4) {
    int i = blockIdx.x * blockDim.x + threadIdx.x;
    if (i < e4) {
        int4 s = __ldg(src4 + i);
        int4 d = __ldg(dst4 + i);
        g_csr[atomicAdd(&g_off[d.x], 1)] = s.x;
        g_csr[atomicAdd(&g_off[d.y], 1)] = s.y;
        g_csr[atomicAdd(&g_off[d.z], 1)] = s.z;
        g_csr[atomicAdd(&g_off[d.w], 1)] = s.w;
    }
}

// ---------------------------------------------------------------------------
// 4) gather: aggh[v] = fp16( norm_dst[v] * sum_{s in in(v)} xh[s] )
//    8 lanes per node, lane c reads one uint4 (8 halves, 16B) per edge.
// ---------------------------------------------------------------------------
__global__ void gather_kernel(int n) {
    int tid = threadIdx.x;
    int node = blockIdx.x * 32 + (tid >> 3);
    if (node >= n) return;
    int c = tid & 7;
    int deg = __ldg(&g_deg_in[node]);
    int start = __ldg(&g_off[node]) - deg;
    const uint4* xr = (const uint4*)g_xh;

    float2 a0 = {0.f, 0.f}, a1 = {0.f, 0.f}, a2 = {0.f, 0.f}, a3 = {0.f, 0.f};
    int j = 0;
    for (; j + 1 < deg; j += 2) {
        int s0 = __ldg(&g_csr[start + j]);
        int s1 = __ldg(&g_csr[start + j + 1]);
        uint4 v0 = __ldg(xr + (size_t)s0 * 8 + c);
        uint4 v1 = __ldg(xr + (size_t)s1 * 8 + c);
        float2 f;
        f = __half22float2(*(__half2*)&v0.x); a0.x += f.x; a0.y += f.y;
        f = __half22float2(*(__half2*)&v0.y); a1.x += f.x; a1.y += f.y;
        f = __half22float2(*(__half2*)&v0.z); a2.x += f.x; a2.y += f.y;
        f = __half22float2(*(__half2*)&v0.w); a3.x += f.x; a3.y += f.y;
        f = __half22float2(*(__half2*)&v1.x); a0.x += f.x; a0.y += f.y;
        f = __half22float2(*(__half2*)&v1.y); a1.x += f.x; a1.y += f.y;
        f = __half22float2(*(__half2*)&v1.z); a2.x += f.x; a2.y += f.y;
        f = __half22float2(*(__half2*)&v1.w); a3.x += f.x; a3.y += f.y;
    }
    if (j < deg) {
        int s = __ldg(&g_csr[start + j]);
        uint4 v = __ldg(xr + (size_t)s * 8 + c);
        float2 f;
        f = __half22float2(*(__half2*)&v.x); a0.x += f.x; a0.y += f.y;
        f = __half22float2(*(__half2*)&v.y); a1.x += f.x; a1.y += f.y;
        f = __half22float2(*(__half2*)&v.z); a2.x += f.x; a2.y += f.y;
        f = __half22float2(*(__half2*)&v.w); a3.x += f.x; a3.y += f.y;
    }
    float nd = rsqrtf((float)(deg < 1 ? 1 : deg));
    __half2 h0 = __floats2half2_rn(a0.x * nd, a0.y * nd);
    __half2 h1 = __floats2half2_rn(a1.x * nd, a1.y * nd);
    __half2 h2 = __floats2half2_rn(a2.x * nd, a2.y * nd);
    __half2 h3 = __floats2half2_rn(a3.x * nd, a3.y * nd);
    uint4 o;
    o.x = *(unsigned*)&h0; o.y = *(unsigned*)&h1;
    o.z = *(unsigned*)&h2; o.w = *(unsigned*)&h3;
    ((uint4*)g_aggh)[(size_t)node * 8 + c] = o;
}

// ---------------------------------------------------------------------------
// 5) GEMM via tensor cores: h2 = aggh @ W + b, fused BN stats.
//    256 rows/block, 8 warps; warp tile 32x64; mma.m16n8k16 f16->f32.
// ---------------------------------------------------------------------------
__global__ void __launch_bounds__(256)
gemm_bn_kernel(const float* __restrict__ W,
               const float* __restrict__ bias, int n) {
    __shared__ __align__(16) __half Ah[256][72];  // row-major [row][k], pad 72
    __shared__ __align__(16) __half Wt[64][72];   // transposed [n][k], pad 72
    __shared__ float bsm[DIM];
    __shared__ float cs[DIM];
    __shared__ float css[DIM];

    int tid = threadIdx.x;
    int lane = tid & 31;
    int warp = tid >> 5;
    int r0 = blockIdx.x * 256;

    // load A rows (fp16): thread t copies row r0+t (8 x uint4)
    {
        int gr = r0 + tid;
        uint4* dstp = (uint4*)&Ah[tid][0];
        if (gr < n) {
            const uint4* srcp = (const uint4*)(g_aggh + (size_t)gr * DIM);
            #pragma unroll
            for (int i = 0; i < 8; i++) dstp[i] = srcp[i];
        } else {
            #pragma unroll
            for (int i = 0; i < 8; i++) dstp[i] = make_uint4(0, 0, 0, 0);
        }
    }
    // W (fp32 [k][n]) -> Wt fp16 [n][k]
    #pragma unroll
    for (int j = 0; j < 16; j++) {
        int e = tid + j * 256;
        int k = e >> 6, nn = e & 63;
        Wt[nn][k] = __float2half(__ldg(W + e));
    }
    if (tid < DIM) { bsm[tid] = __ldg(bias + tid); cs[tid] = 0.f; css[tid] = 0.f; }
    __syncthreads();

    int wr = warp * 32;           // warp's row base within tile
    int g = lane >> 2;            // group id 0..7
    int c2 = (lane & 3) * 2;      // col pair base
    float d[2][8][4] = {};

    #pragma unroll
    for (int ks = 0; ks < 4; ks++) {
        int k0 = ks * 16;
        unsigned a[2][4];
        #pragma unroll
        for (int mt = 0; mt < 2; mt++) {
            int rr = wr + mt * 16;
            a[mt][0] = *(unsigned*)&Ah[rr + g][k0 + c2];
            a[mt][1] = *(unsigned*)&Ah[rr + g + 8][k0 + c2];
            a[mt][2] = *(unsigned*)&Ah[rr + g][k0 + c2 + 8];
            a[mt][3] = *(unsigned*)&Ah[rr + g + 8][k0 + c2 + 8];
        }
        #pragma unroll
        for (int nt = 0; nt < 8; nt++) {
            unsigned bf[2];
            bf[0] = *(unsigned*)&Wt[nt * 8 + g][k0 + c2];
            bf[1] = *(unsigned*)&Wt[nt * 8 + g][k0 + c2 + 8];
            mma_16816(d[0][nt], a[0], bf);
            mma_16816(d[1][nt], a[1], bf);
        }
    }

    // epilogue: bias, store, BN partial sums
    #pragma unroll
    for (int nt = 0; nt < 8; nt++) {
        int col = nt * 8 + c2;
        float b0 = bsm[col], b1 = bsm[col + 1];
        float s0 = 0.f, s1 = 0.f, q0 = 0.f, q1 = 0.f;
        #pragma unroll
        for (int mt = 0; mt < 2; mt++) {
            int rlo = r0 + wr + mt * 16 + g;
            int rhi = rlo + 8;
            if (rlo < n) {
                float o0 = d[mt][nt][0] + b0;
                float o1 = d[mt][nt][1] + b1;
                *(float2*)&g_h2[(size_t)rlo * DIM + col] = make_float2(o0, o1);
                s0 += o0; s1 += o1; q0 += o0 * o0; q1 += o1 * o1;
            }
            if (rhi < n) {
                float o0 = d[mt][nt][2] + b0;
                float o1 = d[mt][nt][3] + b1;
                *(float2*)&g_h2[(size_t)rhi * DIM + col] = make_float2(o0, o1);
                s0 += o0; s1 += o1; q0 += o0 * o0; q1 += o1 * o1;
            }
        }
        atomicAdd(&cs[col], s0);  atomicAdd(&cs[col + 1], s1);
        atomicAdd(&css[col], q0); atomicAdd(&css[col + 1], q1);
    }
    __syncthreads();
    if (tid < DIM) {
        atomicAdd(&g_sum[tid], cs[tid]);
        atomicAdd(&g_sumsq[tid], css[tid]);
    }
}

// ---------------------------------------------------------------------------
// 6) BN finalize
// ---------------------------------------------------------------------------
__global__ void bn_finalize_kernel(const float* __restrict__ gamma,
                                   const float* __restrict__ beta, int n) {
    int c = threadIdx.x;
    if (c < DIM) {
        float inv_n = 1.0f / (float)n;
        float mean = g_sum[c] * inv_n;
        float var = g_sumsq[c] * inv_n - mean * mean;
        float inv = rsqrtf(var + EPS);
        float sc = inv * gamma[c];
        g_scale[c] = sc;
        g_shift[c] = beta[c] - mean * sc;
    }
}

// ---------------------------------------------------------------------------
// 7) out = x + relu(h2*scale + shift); tail re-zeroes degree arrays
// ---------------------------------------------------------------------------
__global__ void final_kernel(const float4* __restrict__ x4,
                             float4* __restrict__ out4, int n16) {
    int i = blockIdx.x * blockDim.x + threadIdx.x;
    if (i >= n16) return;
    int c = (i & 15) * 4;
    float4 h = ((const float4*)g_h2)[i];
    float4 xv = __ldg(x4 + i);
    float4 o;
    o.x = xv.x + fmaxf(h.x * g_scale[c + 0] + g_shift[c + 0], 0.f);
    o.y = xv.y + fmaxf(h.y * g_scale[c + 1] + g_shift[c + 1], 0.f);
    o.z = xv.z + fmaxf(h.z * g_scale[c + 2] + g_shift[c + 2], 0.f);
    o.w = xv.w + fmaxf(h.w * g_scale[c + 3] + g_shift[c + 3], 0.f);
    out4[i] = o;
    int node = i >> 4;
    if ((i & 15) == 0) {
        g_deg_out[node] = 0;
        g_deg_in[node] = 0;
    }
}

// ---------------------------------------------------------------------------
extern "C" void kernel_launch(void* const* d_in, const int* in_sizes, int n_in,
                              void* d_out, int out_size) {
    const float* x     = (const float*)d_in[0];
    const int*   src   = (const int*)d_in[1];
    const int*   dst   = (const int*)d_in[2];
    const float* W     = (const float*)d_in[3];
    const float* b     = (const float*)d_in[4];
    const float* gamma = (const float*)d_in[5];
    const float* beta  = (const float*)d_in[6];

    int n = in_sizes[0] / DIM;   // 100000
    int e = in_sizes[1];         // 1600000
    int e4 = e / 4;
    int nb = (n + SCAN_B - 1) / SCAN_B;

    deg_kernel<<<(e4 + 255) / 256, 256>>>((const int4*)src, (const int4*)dst, e4);
    scanA_kernel<<<nb, SCAN_B>>>(n);
    scanB_kernel<<<1, SCAN_B>>>(nb);
    prep_kernel<<<(n * 16 + 255) / 256, 256>>>((const float4*)x, n * 16);
    fill_kernel<<<(e4 + 255) / 256, 256>>>((const int4*)src, (const int4*)dst, e4);
    gather_kernel<<<(n + 31) / 32, 256>>>(n);
    gemm_bn_kernel<<<(n + 255) / 256, 256>>>(W, b, n);
    bn_finalize_kernel<<<1, 64>>>(gamma, beta, n);
    final_kernel<<<(n * 16 + 255) / 256, 256>>>((const float4*)x, (float4*)d_out, n * 16);
}

// round 7
// speedup vs baseline: 1.2817x; 1.2817x over previous
#include <cuda_runtime.h>
#include <cuda_fp16.h>

#define N_NODES 100000
#define N_EDGES 1600000
#define DIM 64
#define EPS 1e-5f
#define SCAN_B 512

// ---- scratch (device globals; zero-initialized at module load) ----
__device__ __align__(16) __half g_aggh[N_NODES * DIM];  // gathered features (fp16)
__device__ __align__(16) float  g_h2[N_NODES * DIM];    // post-GEMM activations
__device__ __align__(16) __half g_xh[N_NODES * DIM];    // fp16 prescaled x
__device__ __align__(16) __half g_wth[DIM * DIM];       // W transposed, fp16 [n][k]
__device__ int   g_deg_out[N_NODES];   // zeroed at end of final_kernel
__device__ int   g_deg_in[N_NODES];    // zeroed at end of final_kernel
__device__ int   g_off[N_NODES];       // CSR offsets; after fill: end offsets
__device__ int   g_csr[N_EDGES];
__device__ int   g_bsum[SCAN_B];
__device__ int   g_boff[SCAN_B];
__device__ float g_sum[DIM];
__device__ float g_sumsq[DIM];
__device__ float g_scale[DIM];
__device__ float g_shift[DIM];

__device__ __forceinline__ void mma_16816(float* d, const unsigned* a, const unsigned* b) {
    asm volatile(
        "mma.sync.aligned.m16n8k16.row.col.f32.f16.f16.f32 "
        "{%0,%1,%2,%3}, {%4,%5,%6,%7}, {%8,%9}, {%0,%1,%2,%3};"
        : "+f"(d[0]), "+f"(d[1]), "+f"(d[2]), "+f"(d[3])
        : "r"(a[0]), "r"(a[1]), "r"(a[2]), "r"(a[3]), "r"(b[0]), "r"(b[1]));
}

// ---------------------------------------------------------------------------
// 1) degree histogram (both directions), 4 edges per thread via int4
// ---------------------------------------------------------------------------
__global__ void deg_kernel(const int4* __restrict__ src4,
                           const int4* __restrict__ dst4, int e4) {
    int i = blockIdx.x * blockDim.x + threadIdx.x;
    if (i < e4) {
        int4 s = __ldg(src4 + i);
        int4 d = __ldg(dst4 + i);
        atomicAdd(&g_deg_out[s.x], 1); atomicAdd(&g_deg_out[s.y], 1);
        atomicAdd(&g_deg_out[s.z], 1); atomicAdd(&g_deg_out[s.w], 1);
        atomicAdd(&g_deg_in[d.x], 1);  atomicAdd(&g_deg_in[d.y], 1);
        atomicAdd(&g_deg_in[d.z], 1);  atomicAdd(&g_deg_in[d.w], 1);
    }
}

// ---------------------------------------------------------------------------
// 2a) per-block exclusive scan of deg_in
// ---------------------------------------------------------------------------
__global__ void scanA_kernel(int n) {
    __shared__ int sm[SCAN_B];
    int t = threadIdx.x;
    int i = blockIdx.x * SCAN_B + t;
    int v = (i < n) ? g_deg_in[i] : 0;
    sm[t] = v;
    __syncthreads();
    #pragma unroll
    for (int off = 1; off < SCAN_B; off <<= 1) {
        int a = (t >= off) ? sm[t - off] : 0;
        __syncthreads();
        sm[t] += a;
        __syncthreads();
    }
    if (i < n) g_off[i] = sm[t] - v;
    if (t == SCAN_B - 1) g_bsum[blockIdx.x] = sm[t];
}

// ---------------------------------------------------------------------------
// 2b) scan of block sums; zero BN accumulators; build fp16 W^T
// ---------------------------------------------------------------------------
__global__ void scanB_kernel(const float* __restrict__ W, int nb) {
    __shared__ int sm[SCAN_B];
    int t = threadIdx.x;
    int v = (t < nb) ? g_bsum[t] : 0;
    sm[t] = v;
    __syncthreads();
    #pragma unroll
    for (int off = 1; off < SCAN_B; off <<= 1) {
        int a = (t >= off) ? sm[t - off] : 0;
        __syncthreads();
        sm[t] += a;
        __syncthreads();
    }
    if (t < nb) g_boff[t] = sm[t] - v;
    if (t < DIM) { g_sum[t] = 0.f; g_sumsq[t] = 0.f; }
    // W fp32 [k][n] -> g_wth fp16 [n][k]
    #pragma unroll
    for (int j = 0; j < 8; j++) {
        int e = t + j * SCAN_B;            // 0..4095
        int nn = e >> 6, k = e & 63;
        g_wth[nn * DIM + k] = __float2half(__ldg(W + k * DIM + nn));
    }
}

// ---------------------------------------------------------------------------
// 2c) prep: finalize offsets + prescale xh = fp16(x * norm_src)
// ---------------------------------------------------------------------------
__global__ void prep_kernel(const float4* __restrict__ x4, int n16) {
    int i = blockIdx.x * blockDim.x + threadIdx.x;
    if (i >= n16) return;
    int node = i >> 4;
    int c = i & 15;
    if (c == 0) g_off[node] += g_boff[node >> 9];
    int d = __ldg(&g_deg_out[node]);
    float ns = rsqrtf((float)(d < 1 ? 1 : d));
    float4 v = __ldg(x4 + i);
    __half2 h0 = __floats2half2_rn(v.x * ns, v.y * ns);
    __half2 h1 = __floats2half2_rn(v.z * ns, v.w * ns);
    ((__half2*)g_xh)[i * 2 + 0] = h0;
    ((__half2*)g_xh)[i * 2 + 1] = h1;
}

// ---------------------------------------------------------------------------
// 3) CSR bucket fill: bumps g_off (afterwards g_off[i] = end offset of row i)
// ---------------------------------------------------------------------------
__global__ void fill_kernel(const int4* __restrict__ src4,
                            const int4* __restrict__ dst4, int e4) {
    int i = blockIdx.x * blockDim.x + threadIdx.x;
    if (i < e4) {
        int4 s = __ldg(src4 + i);
        int4 d = __ldg(dst4 + i);
        g_csr[atomicAdd(&g_off[d.x], 1)] = s.x;
        g_csr[atomicAdd(&g_off[d.y], 1)] = s.y;
        g_csr[atomicAdd(&g_off[d.z], 1)] = s.z;
        g_csr[atomicAdd(&g_off[d.w], 1)] = s.w;
    }
}

// ---------------------------------------------------------------------------
// 4) gather: aggh[v] = fp16( norm_dst[v] * sum_{s in in(v)} xh[s] )
//    8 lanes per node, lane c reads one uint4 (8 halves, 16B) per edge.
// ---------------------------------------------------------------------------
__global__ void gather_kernel(int n) {
    int tid = threadIdx.x;
    int node = blockIdx.x * 32 + (tid >> 3);
    if (node >= n) return;
    int c = tid & 7;
    int deg = __ldg(&g_deg_in[node]);
    int start = __ldg(&g_off[node]) - deg;
    const uint4* xr = (const uint4*)g_xh;

    float2 a0 = {0.f, 0.f}, a1 = {0.f, 0.f}, a2 = {0.f, 0.f}, a3 = {0.f, 0.f};
    int j = 0;
    for (; j + 1 < deg; j += 2) {
        int s0 = __ldg(&g_csr[start + j]);
        int s1 = __ldg(&g_csr[start + j + 1]);
        uint4 v0 = __ldg(xr + (size_t)s0 * 8 + c);
        uint4 v1 = __ldg(xr + (size_t)s1 * 8 + c);
        float2 f;
        f = __half22float2(*(__half2*)&v0.x); a0.x += f.x; a0.y += f.y;
        f = __half22float2(*(__half2*)&v0.y); a1.x += f.x; a1.y += f.y;
        f = __half22float2(*(__half2*)&v0.z); a2.x += f.x; a2.y += f.y;
        f = __half22float2(*(__half2*)&v0.w); a3.x += f.x; a3.y += f.y;
        f = __half22float2(*(__half2*)&v1.x); a0.x += f.x; a0.y += f.y;
        f = __half22float2(*(__half2*)&v1.y); a1.x += f.x; a1.y += f.y;
        f = __half22float2(*(__half2*)&v1.z); a2.x += f.x; a2.y += f.y;
        f = __half22float2(*(__half2*)&v1.w); a3.x += f.x; a3.y += f.y;
    }
    if (j < deg) {
        int s = __ldg(&g_csr[start + j]);
        uint4 v = __ldg(xr + (size_t)s * 8 + c);
        float2 f;
        f = __half22float2(*(__half2*)&v.x); a0.x += f.x; a0.y += f.y;
        f = __half22float2(*(__half2*)&v.y); a1.x += f.x; a1.y += f.y;
        f = __half22float2(*(__half2*)&v.z); a2.x += f.x; a2.y += f.y;
        f = __half22float2(*(__half2*)&v.w); a3.x += f.x; a3.y += f.y;
    }
    float nd = rsqrtf((float)(deg < 1 ? 1 : deg));
    __half2 h0 = __floats2half2_rn(a0.x * nd, a0.y * nd);
    __half2 h1 = __floats2half2_rn(a1.x * nd, a1.y * nd);
    __half2 h2 = __floats2half2_rn(a2.x * nd, a2.y * nd);
    __half2 h3 = __floats2half2_rn(a3.x * nd, a3.y * nd);
    uint4 o;
    o.x = *(unsigned*)&h0; o.y = *(unsigned*)&h1;
    o.z = *(unsigned*)&h2; o.w = *(unsigned*)&h3;
    ((uint4*)g_aggh)[(size_t)node * 8 + c] = o;
}

// ---------------------------------------------------------------------------
// 5) GEMM via tensor cores: h2 = aggh @ W + b. Pure (no atomics).
//    128 rows/block, 4 warps; warp tile 32x64; mma.m16n8k16 f16->f32.
// ---------------------------------------------------------------------------
__global__ void __launch_bounds__(128)
gemm_kernel(const float* __restrict__ bias, int n) {
    __shared__ __align__(16) __half Ah[128][72];  // 18KB
    __shared__ __align__(16) __half Wt[64][72];   // 9KB
    __shared__ float bsm[DIM];

    int tid = threadIdx.x;
    int lane = tid & 31;
    int warp = tid >> 5;
    int r0 = blockIdx.x * 128;

    // A rows: thread t copies row r0+t (8 x uint4)
    {
        int gr = r0 + tid;
        uint4* dstp = (uint4*)&Ah[tid][0];
        if (gr < n) {
            const uint4* srcp = (const uint4*)(g_aggh + (size_t)gr * DIM);
            #pragma unroll
            for (int i = 0; i < 8; i++) dstp[i] = srcp[i];
        } else {
            #pragma unroll
            for (int i = 0; i < 8; i++) dstp[i] = make_uint4(0, 0, 0, 0);
        }
    }
    // Wt fp16 [n][k]: 512 uint4, 4 per thread
    #pragma unroll
    for (int j = 0; j < 4; j++) {
        int e = tid + j * 128;
        int nn = e >> 3, kq = e & 7;
        *(uint4*)&Wt[nn][kq * 8] = __ldg((const uint4*)g_wth + e);
    }
    if (tid < DIM) bsm[tid] = __ldg(bias + tid);
    __syncthreads();

    int wr = warp * 32;
    int g = lane >> 2;
    int c2 = (lane & 3) * 2;
    float d[2][8][4] = {};

    #pragma unroll
    for (int ks = 0; ks < 4; ks++) {
        int k0 = ks * 16;
        unsigned a[2][4];
        #pragma unroll
        for (int mt = 0; mt < 2; mt++) {
            int rr = wr + mt * 16;
            a[mt][0] = *(unsigned*)&Ah[rr + g][k0 + c2];
            a[mt][1] = *(unsigned*)&Ah[rr + g + 8][k0 + c2];
            a[mt][2] = *(unsigned*)&Ah[rr + g][k0 + c2 + 8];
            a[mt][3] = *(unsigned*)&Ah[rr + g + 8][k0 + c2 + 8];
        }
        #pragma unroll
        for (int nt = 0; nt < 8; nt++) {
            unsigned bf[2];
            bf[0] = *(unsigned*)&Wt[nt * 8 + g][k0 + c2];
            bf[1] = *(unsigned*)&Wt[nt * 8 + g][k0 + c2 + 8];
            mma_16816(d[0][nt], a[0], bf);
            mma_16816(d[1][nt], a[1], bf);
        }
    }

    // epilogue: bias + store
    #pragma unroll
    for (int nt = 0; nt < 8; nt++) {
        int col = nt * 8 + c2;
        float b0 = bsm[col], b1 = bsm[col + 1];
        #pragma unroll
        for (int mt = 0; mt < 2; mt++) {
            int rlo = r0 + wr + mt * 16 + g;
            int rhi = rlo + 8;
            if (rlo < n)
                *(float2*)&g_h2[(size_t)rlo * DIM + col] =
                    make_float2(d[mt][nt][0] + b0, d[mt][nt][1] + b1);
            if (rhi < n)
                *(float2*)&g_h2[(size_t)rhi * DIM + col] =
                    make_float2(d[mt][nt][2] + b0, d[mt][nt][3] + b1);
        }
    }
}

// ---------------------------------------------------------------------------
// 6) BN stats: register-accumulated column sums over h2.
//    Grid-stride float4; each thread's 4 columns are fixed.
// ---------------------------------------------------------------------------
__global__ void __launch_bounds__(256)
stats_kernel(int n16) {
    __shared__ float cs[DIM];
    __shared__ float css[DIM];
    int tid = threadIdx.x;
    if (tid < DIM) { cs[tid] = 0.f; css[tid] = 0.f; }
    __syncthreads();

    float s0 = 0.f, s1 = 0.f, s2 = 0.f, s3 = 0.f;
    float q0 = 0.f, q1 = 0.f, q2 = 0.f, q3 = 0.f;
    int stride = gridDim.x * blockDim.x;   // multiple of 16
    for (int i = blockIdx.x * blockDim.x + tid; i < n16; i += stride) {
        float4 h = ((const float4*)g_h2)[i];
        s0 += h.x; q0 += h.x * h.x;
        s1 += h.y; q1 += h.y * h.y;
        s2 += h.z; q2 += h.z * h.z;
        s3 += h.w; q3 += h.w * h.w;
    }
    int c = (tid & 15) * 4;
    atomicAdd(&cs[c + 0], s0); atomicAdd(&css[c + 0], q0);
    atomicAdd(&cs[c + 1], s1); atomicAdd(&css[c + 1], q1);
    atomicAdd(&cs[c + 2], s2); atomicAdd(&css[c + 2], q2);
    atomicAdd(&cs[c + 3], s3); atomicAdd(&css[c + 3], q3);
    __syncthreads();
    if (tid < DIM) {
        atomicAdd(&g_sum[tid], cs[tid]);
        atomicAdd(&g_sumsq[tid], css[tid]);
    }
}

// ---------------------------------------------------------------------------
// 7) BN finalize
// ---------------------------------------------------------------------------
__global__ void bn_finalize_kernel(const float* __restrict__ gamma,
                                   const float* __restrict__ beta, int n) {
    int c = threadIdx.x;
    if (c < DIM) {
        float inv_n = 1.0f / (float)n;
        float mean = g_sum[c] * inv_n;
        float var = g_sumsq[c] * inv_n - mean * mean;
        float inv = rsqrtf(var + EPS);
        float sc = inv * gamma[c];
        g_scale[c] = sc;
        g_shift[c] = beta[c] - mean * sc;
    }
}

// ---------------------------------------------------------------------------
// 8) out = x + relu(h2*scale + shift); tail re-zeroes degree arrays
// ---------------------------------------------------------------------------
__global__ void final_kernel(const float4* __restrict__ x4,
                             float4* __restrict__ out4, int n16) {
    int i = blockIdx.x * blockDim.x + threadIdx.x;
    if (i >= n16) return;
    int c = (i & 15) * 4;
    float4 h = ((const float4*)g_h2)[i];
    float4 xv = __ldg(x4 + i);
    float4 o;
    o.x = xv.x + fmaxf(h.x * g_scale[c + 0] + g_shift[c + 0], 0.f);
    o.y = xv.y + fmaxf(h.y * g_scale[c + 1] + g_shift[c + 1], 0.f);
    o.z = xv.z + fmaxf(h.z * g_scale[c + 2] + g_shift[c + 2], 0.f);
    o.w = xv.w + fmaxf(h.w * g_scale[c + 3] + g_shift[c + 3], 0.f);
    out4[i] = o;
    int node = i >> 4;
    if ((i & 15) == 0) {
        g_deg_out[node] = 0;
        g_deg_in[node] = 0;
    }
}

// ---------------------------------------------------------------------------
extern "C" void kernel_launch(void* const* d_in, const int* in_sizes, int n_in,
                              void* d_out, int out_size) {
    const float* x     = (const float*)d_in[0];
    const int*   src   = (const int*)d_in[1];
    const int*   dst   = (const int*)d_in[2];
    const float* W     = (const float*)d_in[3];
    const float* b     = (const float*)d_in[4];
    const float* gamma = (const float*)d_in[5];
    const float* beta  = (const float*)d_in[6];

    int n = in_sizes[0] / DIM;   // 100000
    int e = in_sizes[1];         // 1600000
    int e4 = e / 4;
    int nb = (n + SCAN_B - 1) / SCAN_B;

    deg_kernel<<<(e4 + 255) / 256, 256>>>((const int4*)src, (const int4*)dst, e4);
    scanA_kernel<<<nb, SCAN_B>>>(n);
    scanB_kernel<<<1, SCAN_B>>>(W, nb);
    prep_kernel<<<(n * 16 + 255) / 256, 256>>>((const float4*)x, n * 16);
    fill_kernel<<<(e4 + 255) / 256, 256>>>((const int4*)src, (const int4*)dst, e4);
    gather_kernel<<<(n + 31) / 32, 256>>>(n);
    gemm_kernel<<<(n + 127) / 128, 128>>>(b, n);
    stats_kernel<<<296, 256>>>(n * 16);
    bn_finalize_kernel<<<1, 64>>>(gamma, beta, n);
    final_kernel<<<(n * 16 + 255) / 256, 256>>>((const float4*)x, (float4*)d_out, n * 16);
}

// round 8
// speedup vs baseline: 1.3513x; 1.0543x over previous
#include <cuda_runtime.h>
#include <cuda_fp16.h>

#define N_NODES 100000
#define N_EDGES 1600000
#define DIM 64
#define EPS 1e-5f
#define SCAN_B 512

// ---- scratch (device globals; zero-initialized at module load) ----
__device__ __align__(16) __half g_aggh[N_NODES * DIM];  // gathered features (fp16)
__device__ __align__(16) __half g_h2h[N_NODES * DIM];   // post-GEMM activations (fp16)
__device__ __align__(16) __half g_xh[N_NODES * DIM];    // fp16 prescaled x
__device__ __align__(16) __half g_wth[DIM * DIM];       // W transposed, fp16 [n][k]
__device__ int   g_deg_out[N_NODES];   // zeroed at end of final_kernel
__device__ int   g_deg_in[N_NODES];    // zeroed at end of final_kernel
__device__ int   g_off[N_NODES];       // CSR offsets; after fill: end offsets
__device__ int   g_csr[N_EDGES];
__device__ int   g_bsum[SCAN_B];
__device__ int   g_boff[SCAN_B];
__device__ float g_sum[DIM];
__device__ float g_sumsq[DIM];
__device__ float g_scale[DIM];
__device__ float g_shift[DIM];

__device__ __forceinline__ void mma_16816(float* d, const unsigned* a, const unsigned* b) {
    asm volatile(
        "mma.sync.aligned.m16n8k16.row.col.f32.f16.f16.f32 "
        "{%0,%1,%2,%3}, {%4,%5,%6,%7}, {%8,%9}, {%0,%1,%2,%3};"
        : "+f"(d[0]), "+f"(d[1]), "+f"(d[2]), "+f"(d[3])
        : "r"(a[0]), "r"(a[1]), "r"(a[2]), "r"(a[3]), "r"(b[0]), "r"(b[1]));
}

// ---------------------------------------------------------------------------
// 1) degree histogram (both directions), 4 edges per thread via int4
// ---------------------------------------------------------------------------
__global__ void deg_kernel(const int4* __restrict__ src4,
                           const int4* __restrict__ dst4, int e4) {
    int i = blockIdx.x * blockDim.x + threadIdx.x;
    if (i < e4) {
        int4 s = __ldg(src4 + i);
        int4 d = __ldg(dst4 + i);
        atomicAdd(&g_deg_out[s.x], 1); atomicAdd(&g_deg_out[s.y], 1);
        atomicAdd(&g_deg_out[s.z], 1); atomicAdd(&g_deg_out[s.w], 1);
        atomicAdd(&g_deg_in[d.x], 1);  atomicAdd(&g_deg_in[d.y], 1);
        atomicAdd(&g_deg_in[d.z], 1);  atomicAdd(&g_deg_in[d.w], 1);
    }
}

// ---------------------------------------------------------------------------
// 2a) per-block exclusive scan of deg_in
// ---------------------------------------------------------------------------
__global__ void scanA_kernel(int n) {
    __shared__ int sm[SCAN_B];
    int t = threadIdx.x;
    int i = blockIdx.x * SCAN_B + t;
    int v = (i < n) ? g_deg_in[i] : 0;
    sm[t] = v;
    __syncthreads();
    #pragma unroll
    for (int off = 1; off < SCAN_B; off <<= 1) {
        int a = (t >= off) ? sm[t - off] : 0;
        __syncthreads();
        sm[t] += a;
        __syncthreads();
    }
    if (i < n) g_off[i] = sm[t] - v;
    if (t == SCAN_B - 1) g_bsum[blockIdx.x] = sm[t];
}

// ---------------------------------------------------------------------------
// 2b) scan of block sums; zero BN accumulators; build fp16 W^T
// ---------------------------------------------------------------------------
__global__ void scanB_kernel(const float* __restrict__ W, int nb) {
    __shared__ int sm[SCAN_B];
    int t = threadIdx.x;
    int v = (t < nb) ? g_bsum[t] : 0;
    sm[t] = v;
    __syncthreads();
    #pragma unroll
    for (int off = 1; off < SCAN_B; off <<= 1) {
        int a = (t >= off) ? sm[t - off] : 0;
        __syncthreads();
        sm[t] += a;
        __syncthreads();
    }
    if (t < nb) g_boff[t] = sm[t] - v;
    if (t < DIM) { g_sum[t] = 0.f; g_sumsq[t] = 0.f; }
    // W fp32 [k][n] -> g_wth fp16 [n][k]
    #pragma unroll
    for (int j = 0; j < 8; j++) {
        int e = t + j * SCAN_B;            // 0..4095
        int nn = e >> 6, k = e & 63;
        g_wth[nn * DIM + k] = __float2half(__ldg(W + k * DIM + nn));
    }
}

// ---------------------------------------------------------------------------
// 2c) prep: finalize offsets + prescale xh = fp16(x * norm_src)
// ---------------------------------------------------------------------------
__global__ void prep_kernel(const float4* __restrict__ x4, int n16) {
    int i = blockIdx.x * blockDim.x + threadIdx.x;
    if (i >= n16) return;
    int node = i >> 4;
    int c = i & 15;
    if (c == 0) g_off[node] += g_boff[node >> 9];
    int d = __ldg(&g_deg_out[node]);
    float ns = rsqrtf((float)(d < 1 ? 1 : d));
    float4 v = __ldg(x4 + i);
    __half2 h0 = __floats2half2_rn(v.x * ns, v.y * ns);
    __half2 h1 = __floats2half2_rn(v.z * ns, v.w * ns);
    ((__half2*)g_xh)[i * 2 + 0] = h0;
    ((__half2*)g_xh)[i * 2 + 1] = h1;
}

// ---------------------------------------------------------------------------
// 3) CSR bucket fill: bumps g_off (afterwards g_off[i] = end offset of row i)
// ---------------------------------------------------------------------------
__global__ void fill_kernel(const int4* __restrict__ src4,
                            const int4* __restrict__ dst4, int e4) {
    int i = blockIdx.x * blockDim.x + threadIdx.x;
    if (i < e4) {
        int4 s = __ldg(src4 + i);
        int4 d = __ldg(dst4 + i);
        g_csr[atomicAdd(&g_off[d.x], 1)] = s.x;
        g_csr[atomicAdd(&g_off[d.y], 1)] = s.y;
        g_csr[atomicAdd(&g_off[d.z], 1)] = s.z;
        g_csr[atomicAdd(&g_off[d.w], 1)] = s.w;
    }
}

// ---------------------------------------------------------------------------
// 4) gather: aggh[v] = fp16( norm_dst[v] * sum_{s in in(v)} xh[s] )
//    8 lanes per node, lane c reads one uint4 (8 halves, 16B) per edge.
// ---------------------------------------------------------------------------
__global__ void gather_kernel(int n) {
    int tid = threadIdx.x;
    int node = blockIdx.x * 32 + (tid >> 3);
    if (node >= n) return;
    int c = tid & 7;
    int deg = __ldg(&g_deg_in[node]);
    int start = __ldg(&g_off[node]) - deg;
    const uint4* xr = (const uint4*)g_xh;

    float2 a0 = {0.f, 0.f}, a1 = {0.f, 0.f}, a2 = {0.f, 0.f}, a3 = {0.f, 0.f};
    int j = 0;
    for (; j + 1 < deg; j += 2) {
        int s0 = __ldg(&g_csr[start + j]);
        int s1 = __ldg(&g_csr[start + j + 1]);
        uint4 v0 = __ldg(xr + (size_t)s0 * 8 + c);
        uint4 v1 = __ldg(xr + (size_t)s1 * 8 + c);
        float2 f;
        f = __half22float2(*(__half2*)&v0.x); a0.x += f.x; a0.y += f.y;
        f = __half22float2(*(__half2*)&v0.y); a1.x += f.x; a1.y += f.y;
        f = __half22float2(*(__half2*)&v0.z); a2.x += f.x; a2.y += f.y;
        f = __half22float2(*(__half2*)&v0.w); a3.x += f.x; a3.y += f.y;
        f = __half22float2(*(__half2*)&v1.x); a0.x += f.x; a0.y += f.y;
        f = __half22float2(*(__half2*)&v1.y); a1.x += f.x; a1.y += f.y;
        f = __half22float2(*(__half2*)&v1.z); a2.x += f.x; a2.y += f.y;
        f = __half22float2(*(__half2*)&v1.w); a3.x += f.x; a3.y += f.y;
    }
    if (j < deg) {
        int s = __ldg(&g_csr[start + j]);
        uint4 v = __ldg(xr + (size_t)s * 8 + c);
        float2 f;
        f = __half22float2(*(__half2*)&v.x); a0.x += f.x; a0.y += f.y;
        f = __half22float2(*(__half2*)&v.y); a1.x += f.x; a1.y += f.y;
        f = __half22float2(*(__half2*)&v.z); a2.x += f.x; a2.y += f.y;
        f = __half22float2(*(__half2*)&v.w); a3.x += f.x; a3.y += f.y;
    }
    float nd = rsqrtf((float)(deg < 1 ? 1 : deg));
    __half2 h0 = __floats2half2_rn(a0.x * nd, a0.y * nd);
    __half2 h1 = __floats2half2_rn(a1.x * nd, a1.y * nd);
    __half2 h2 = __floats2half2_rn(a2.x * nd, a2.y * nd);
    __half2 h3 = __floats2half2_rn(a3.x * nd, a3.y * nd);
    uint4 o;
    o.x = *(unsigned*)&h0; o.y = *(unsigned*)&h1;
    o.z = *(unsigned*)&h2; o.w = *(unsigned*)&h3;
    ((uint4*)g_aggh)[(size_t)node * 8 + c] = o;
}

// ---------------------------------------------------------------------------
// 5) GEMM via tensor cores: h2h = fp16(aggh @ W + b), fused BN stats
//    (warp-shuffle reduced — lanes g==0 only touch smem; 128 atomics/block).
//    128 rows/block, 4 warps; warp tile 32x64; mma.m16n8k16 f16->f32.
// ---------------------------------------------------------------------------
__global__ void __launch_bounds__(128)
gemm_kernel(const float* __restrict__ bias, int n) {
    __shared__ __align__(16) __half Ah[128][72];  // 18KB
    __shared__ __align__(16) __half Wt[64][72];   // 9KB
    __shared__ float bsm[DIM];
    __shared__ float cs[DIM];
    __shared__ float css[DIM];

    int tid = threadIdx.x;
    int lane = tid & 31;
    int warp = tid >> 5;
    int r0 = blockIdx.x * 128;

    // A rows: thread t copies row r0+t (8 x uint4)
    {
        int gr = r0 + tid;
        uint4* dstp = (uint4*)&Ah[tid][0];
        if (gr < n) {
            const uint4* srcp = (const uint4*)(g_aggh + (size_t)gr * DIM);
            #pragma unroll
            for (int i = 0; i < 8; i++) dstp[i] = srcp[i];
        } else {
            #pragma unroll
            for (int i = 0; i < 8; i++) dstp[i] = make_uint4(0, 0, 0, 0);
        }
    }
    // Wt fp16 [n][k]: 512 uint4, 4 per thread
    #pragma unroll
    for (int j = 0; j < 4; j++) {
        int e = tid + j * 128;
        int nn = e >> 3, kq = e & 7;
        *(uint4*)&Wt[nn][kq * 8] = __ldg((const uint4*)g_wth + e);
    }
    if (tid < DIM) { bsm[tid] = __ldg(bias + tid); cs[tid] = 0.f; css[tid] = 0.f; }
    __syncthreads();

    int wr = warp * 32;
    int g = lane >> 2;
    int c2 = (lane & 3) * 2;
    float d[2][8][4] = {};

    #pragma unroll
    for (int ks = 0; ks < 4; ks++) {
        int k0 = ks * 16;
        unsigned a[2][4];
        #pragma unroll
        for (int mt = 0; mt < 2; mt++) {
            int rr = wr + mt * 16;
            a[mt][0] = *(unsigned*)&Ah[rr + g][k0 + c2];
            a[mt][1] = *(unsigned*)&Ah[rr + g + 8][k0 + c2];
            a[mt][2] = *(unsigned*)&Ah[rr + g][k0 + c2 + 8];
            a[mt][3] = *(unsigned*)&Ah[rr + g + 8][k0 + c2 + 8];
        }
        #pragma unroll
        for (int nt = 0; nt < 8; nt++) {
            unsigned bf[2];
            bf[0] = *(unsigned*)&Wt[nt * 8 + g][k0 + c2];
            bf[1] = *(unsigned*)&Wt[nt * 8 + g][k0 + c2 + 8];
            mma_16816(d[0][nt], a[0], bf);
            mma_16816(d[1][nt], a[1], bf);
        }
    }

    // epilogue: bias + fp16 store + BN partial sums (shuffle-reduced over g)
    #pragma unroll
    for (int nt = 0; nt < 8; nt++) {
        int col = nt * 8 + c2;
        float b0 = bsm[col], b1 = bsm[col + 1];
        float s0 = 0.f, s1 = 0.f, q0 = 0.f, q1 = 0.f;
        #pragma unroll
        for (int mt = 0; mt < 2; mt++) {
            int rlo = r0 + wr + mt * 16 + g;
            int rhi = rlo + 8;
            if (rlo < n) {
                float o0 = d[mt][nt][0] + b0;
                float o1 = d[mt][nt][1] + b1;
                __half2 h = __floats2half2_rn(o0, o1);
                *(unsigned*)&g_h2h[(size_t)rlo * DIM + col] = *(unsigned*)&h;
                s0 += o0; s1 += o1; q0 += o0 * o0; q1 += o1 * o1;
            }
            if (rhi < n) {
                float o0 = d[mt][nt][2] + b0;
                float o1 = d[mt][nt][3] + b1;
                __half2 h = __floats2half2_rn(o0, o1);
                *(unsigned*)&g_h2h[(size_t)rhi * DIM + col] = *(unsigned*)&h;
                s0 += o0; s1 += o1; q0 += o0 * o0; q1 += o1 * o1;
            }
        }
        #pragma unroll
        for (int off = 4; off < 32; off <<= 1) {
            s0 += __shfl_xor_sync(0xffffffffu, s0, off);
            s1 += __shfl_xor_sync(0xffffffffu, s1, off);
            q0 += __shfl_xor_sync(0xffffffffu, q0, off);
            q1 += __shfl_xor_sync(0xffffffffu, q1, off);
        }
        if (g == 0) {
            atomicAdd(&cs[col], s0);  atomicAdd(&cs[col + 1], s1);
            atomicAdd(&css[col], q0); atomicAdd(&css[col + 1], q1);
        }
    }
    __syncthreads();
    if (tid < DIM) {
        atomicAdd(&g_sum[tid], cs[tid]);
        atomicAdd(&g_sumsq[tid], css[tid]);
    }
}

// ---------------------------------------------------------------------------
// 6) BN finalize
// ---------------------------------------------------------------------------
__global__ void bn_finalize_kernel(const float* __restrict__ gamma,
                                   const float* __restrict__ beta, int n) {
    int c = threadIdx.x;
    if (c < DIM) {
        float inv_n = 1.0f / (float)n;
        float mean = g_sum[c] * inv_n;
        float var = g_sumsq[c] * inv_n - mean * mean;
        float inv = rsqrtf(var + EPS);
        float sc = inv * gamma[c];
        g_scale[c] = sc;
        g_shift[c] = beta[c] - mean * sc;
    }
}

// ---------------------------------------------------------------------------
// 7) out = x + relu(h2*scale + shift); tail re-zeroes degree arrays
// ---------------------------------------------------------------------------
__global__ void final_kernel(const float4* __restrict__ x4,
                             float4* __restrict__ out4, int n16) {
    int i = blockIdx.x * blockDim.x + threadIdx.x;
    if (i >= n16) return;
    int c = (i & 15) * 4;
    uint2 hraw = ((const uint2*)g_h2h)[i];
    float2 h01 = __half22float2(*(__half2*)&hraw.x);
    float2 h23 = __half22float2(*(__half2*)&hraw.y);
    float4 xv = __ldg(x4 + i);
    float4 o;
    o.x = xv.x + fmaxf(h01.x * g_scale[c + 0] + g_shift[c + 0], 0.f);
    o.y = xv.y + fmaxf(h01.y * g_scale[c + 1] + g_shift[c + 1], 0.f);
    o.z = xv.z + fmaxf(h23.x * g_scale[c + 2] + g_shift[c + 2], 0.f);
    o.w = xv.w + fmaxf(h23.y * g_scale[c + 3] + g_shift[c + 3], 0.f);
    out4[i] = o;
    int node = i >> 4;
    if ((i & 15) == 0) {
        g_deg_out[node] = 0;
        g_deg_in[node] = 0;
    }
}

// ---------------------------------------------------------------------------
extern "C" void kernel_launch(void* const* d_in, const int* in_sizes, int n_in,
                              void* d_out, int out_size) {
    const float* x     = (const float*)d_in[0];
    const int*   src   = (const int*)d_in[1];
    const int*   dst   = (const int*)d_in[2];
    const float* W     = (const float*)d_in[3];
    const float* b     = (const float*)d_in[4];
    const float* gamma = (const float*)d_in[5];
    const float* beta  = (const float*)d_in[6];

    int n = in_sizes[0] / DIM;   // 100000
    int e = in_sizes[1];         // 1600000
    int e4 = e / 4;
    int nb = (n + SCAN_B - 1) / SCAN_B;

    deg_kernel<<<(e4 + 255) / 256, 256>>>((const int4*)src, (const int4*)dst, e4);
    scanA_kernel<<<nb, SCAN_B>>>(n);
    scanB_kernel<<<1, SCAN_B>>>(W, nb);
    prep_kernel<<<(n * 16 + 255) / 256, 256>>>((const float4*)x, n * 16);
    fill_kernel<<<(e4 + 255) / 256, 256>>>((const int4*)src, (const int4*)dst, e4);
    gather_kernel<<<(n + 31) / 32, 256>>>(n);
    gemm_kernel<<<(n + 127) / 128, 128>>>(b, n);
    bn_finalize_kernel<<<1, 64>>>(gamma, beta, n);
    final_kernel<<<(n * 16 + 255) / 256, 256>>>((const float4*)x, (float4*)d_out, n * 16);
}